// round 1
// baseline (speedup 1.0000x reference)
#include <cuda_runtime.h>
#include <cuda_bf16.h>
#include <math.h>

// ---------------------------------------------------------------------------
// TokenFlowTokenizer: encoder (3x s2 conv) -> codebook argmax -> decoder (3x deconv)
// All activations NHWC fp32. conv2/conv3/deconvs via im2col + SGEMM.
// ---------------------------------------------------------------------------

#define THREADS 256
#define BM 128
#define BN 128
#define BK 16
#define TM 8
#define TN 8

// ---------------- scratch (device globals; no allocation allowed) ----------
__device__ float g_h1  [16u*128u*128u*64u];     // conv1 out NHWC     (16.8M)
__device__ float g_col [134217728u];            // im2col scratch     (134M floats)
__device__ float g_h2  [65536u*128u];           // conv2 out [rows,C]
__device__ float g_feat[16384u*256u];           // conv3 out == flat [B*HW, C]
__device__ float g_q   [16384u*256u];           // quantized NHWC
__device__ float g_d1  [16u*64u*64u*128u];      // deconv1 out NHWC
__device__ float g_d2  [16u*128u*128u*64u];     // deconv2 out NHWC
__device__ float g_wp  [8192u*256u];            // packed weights / cb^T
__device__ unsigned long long g_amax[16384];

// ---------------- helpers ---------------------------------------------------
__device__ __forceinline__ unsigned ford(float f) {
    unsigned u = __float_as_uint(f);
    return (u & 0x80000000u) ? ~u : (u | 0x80000000u);
}

// ---------------- conv1: direct, Cin=3, NCHW in -> NHWC out -----------------
__global__ void conv1_k(const float* __restrict__ x, const float* __restrict__ w,
                        const float* __restrict__ b, float* __restrict__ y)
{
    __shared__ float ws[64 * 48];
    for (int i = threadIdx.x; i < 64 * 48; i += THREADS) ws[i] = w[i];
    __syncthreads();
    unsigned gid = blockIdx.x * THREADS + threadIdx.x;   // 16*128*128*64 = 2^24
    int co = gid & 63;
    int ow = (gid >> 6) & 127;
    int oh = (gid >> 13) & 127;
    int n  = gid >> 20;
    float acc = b[co];
    #pragma unroll
    for (int kh = 0; kh < 4; kh++) {
        int ih = 2 * oh + kh - 1;
        if ((unsigned)ih >= 256u) continue;
        #pragma unroll
        for (int kw = 0; kw < 4; kw++) {
            int iw = 2 * ow + kw - 1;
            if ((unsigned)iw >= 256u) continue;
            #pragma unroll
            for (int ci = 0; ci < 3; ci++) {
                acc += x[((size_t)(n * 3 + ci) * 256 + ih) * 256 + iw]
                     * ws[co * 48 + ci * 16 + kh * 4 + kw];
            }
        }
    }
    y[gid] = fmaxf(acc, 0.f);
}

// ---------------- im2col for stride-2 conv (NHWC input) ---------------------
__global__ void im2col_conv(const float* __restrict__ in, float* __restrict__ A,
                            int Hin, int Win, int C, int Ho, int Wo)
{
    int K = 16 * C;
    int kq = K >> 2;
    long long gid = (long long)blockIdx.x * THREADS + threadIdx.x;
    long long total = (long long)16 * Ho * Wo * kq;
    if (gid >= total) return;
    long long row = gid / kq;
    int k = (int)(gid % kq) * 4;
    int ci = k % C;
    int kidx = k / C;
    int kh = kidx >> 2, kw = kidx & 3;
    int n = (int)(row / (Ho * Wo));
    int rem = (int)(row % (Ho * Wo));
    int oh = rem / Wo, ow = rem % Wo;
    int ih = 2 * oh + kh - 1, iw = 2 * ow + kw - 1;
    float4 v = make_float4(0.f, 0.f, 0.f, 0.f);
    if ((unsigned)ih < (unsigned)Hin && (unsigned)iw < (unsigned)Win)
        v = *reinterpret_cast<const float4*>(in + ((size_t)(n * Hin + ih) * Win + iw) * C + ci);
    *reinterpret_cast<float4*>(A + (size_t)row * K + k) = v;
}

// ---------------- im2col for deconv (4 parity classes, NHWC input) ----------
__global__ void im2col_deconv(const float* __restrict__ in, float* __restrict__ A,
                              int Hq, int Wq, int C)
{
    int K = 4 * C;
    int kq = K >> 2;
    long long perClass = (long long)16 * Hq * Wq * kq;
    long long gid = (long long)blockIdx.x * THREADS + threadIdx.x;
    if (gid >= 4 * perClass) return;
    int cls = (int)(gid / perClass);
    long long g2 = gid % perClass;
    int ph = cls >> 1, pw = cls & 1;
    long long row = g2 / kq;
    int k = (int)(g2 % kq) * 4;
    int ci = k % C;
    int kidx = k / C;
    int th = kidx >> 1, tw = kidx & 1;
    int n = (int)(row / (Hq * Wq));
    int rem = (int)(row % (Hq * Wq));
    int r = rem / Wq, c = rem % Wq;
    int ih = r + th - 1 + ph, iw = c + tw - 1 + pw;
    float4 v = make_float4(0.f, 0.f, 0.f, 0.f);
    if ((unsigned)ih < (unsigned)Hq && (unsigned)iw < (unsigned)Wq)
        v = *reinterpret_cast<const float4*>(in + ((size_t)(n * Hq + ih) * Wq + iw) * C + ci);
    A[(size_t)cls * 16 * Hq * Wq * K + (size_t)row * K + k] = v.x;
    A[(size_t)cls * 16 * Hq * Wq * K + (size_t)row * K + k + 1] = v.y;
    A[(size_t)cls * 16 * Hq * Wq * K + (size_t)row * K + k + 2] = v.z;
    A[(size_t)cls * 16 * Hq * Wq * K + (size_t)row * K + k + 3] = v.w;
}

// ---------------- weight packing --------------------------------------------
// conv: Bp[k,co], k=(kh*4+kw)*Ci+ci  <- w[co,ci,kh,kw]
__global__ void pack_w_conv(const float* __restrict__ w, float* __restrict__ Bp,
                            int Ci, int Co)
{
    int K = 16 * Ci;
    long long gid = (long long)blockIdx.x * THREADS + threadIdx.x;
    if (gid >= (long long)K * Co) return;
    int k = (int)(gid / Co), co = (int)(gid % Co);
    int ci = k % Ci;
    int kidx = k / Ci;
    int kh = kidx >> 2, kw = kidx & 3;
    Bp[gid] = w[(((size_t)co * Ci + ci) * 4 + kh) * 4 + kw];
}

// deconv classes: Bp[cls][k=(th*2+tw)*Ci+ci][co] <- w[co,ci,2th+ph,2tw+pw]
__global__ void pack_w_deconv(const float* __restrict__ w, float* __restrict__ Bp,
                              int Ci, int Co)
{
    int K = 4 * Ci;
    long long gid = (long long)blockIdx.x * THREADS + threadIdx.x;
    if (gid >= (long long)4 * K * Co) return;
    int cls = (int)(gid / ((long long)K * Co));
    long long g2 = gid % ((long long)K * Co);
    int k = (int)(g2 / Co), co = (int)(g2 % Co);
    int ci = k % Ci;
    int kidx = k / Ci;
    int th = kidx >> 1, tw = kidx & 1;
    int kh = 2 * th + (cls >> 1);
    int kw = 2 * tw + (cls & 1);
    Bp[gid] = w[(((size_t)co * Ci + ci) * 4 + kh) * 4 + kw];
}

// cb [8192,256] -> T [256,8192]
__global__ void transpose_cb(const float* __restrict__ cb, float* __restrict__ T)
{
    __shared__ float tile[32][33];
    int xi = blockIdx.x * 32 + threadIdx.x;   // k   in cb (0..255)
    int yi = blockIdx.y * 32 + threadIdx.y;   // code in cb
    #pragma unroll
    for (int j = 0; j < 32; j += 8)
        tile[threadIdx.y + j][threadIdx.x] = cb[(size_t)(yi + j) * 256 + xi];
    __syncthreads();
    int xo = blockIdx.y * 32 + threadIdx.x;   // code in T
    int yo = blockIdx.x * 32 + threadIdx.y;   // k    in T
    #pragma unroll
    for (int j = 0; j < 32; j += 8)
        T[(size_t)(yo + j) * 8192 + xo] = tile[threadIdx.x][threadIdx.y + j];
}

__global__ void init_amax(unsigned long long* am)
{
    int i = blockIdx.x * THREADS + threadIdx.x;
    if (i < 16384) am[i] = 0ull;
}

// ---------------- SGEMM with fused epilogues --------------------------------
// MODE 0: out[row*N+col] = relu?(acc + bias[col])
// MODE 1: parity scatter into NHWC [16, 2Hq, 2Wq, N], class = blockIdx.z
// MODE 2: row-argmax into amax via 64-bit atomicMax key
template<int MODE>
__global__ void __launch_bounds__(256, 2)
gemm_k(const float* __restrict__ A, const float* __restrict__ B,
       int M, int N, int K,
       const float* __restrict__ bias, int relu,
       float* __restrict__ out,
       int Hq, int Wq,
       unsigned long long* __restrict__ amax)
{
    __shared__ float As[BK][BM];
    __shared__ float Bs[BK][BN];
    int tid = threadIdx.x;
    int tx = tid & 15, ty = tid >> 4;
    int z = blockIdx.z;
    int rowBase = blockIdx.y * BM;
    int colBase = blockIdx.x * BN;
    const float* Ab = A + (size_t)z * M * K + (size_t)rowBase * K;
    const float* Bb = B + (size_t)z * K * N;
    float acc[TM][TN];
    #pragma unroll
    for (int j = 0; j < TM; j++)
        #pragma unroll
        for (int i = 0; i < TN; i++) acc[j][i] = 0.f;

    for (int k0 = 0; k0 < K; k0 += BK) {
        #pragma unroll
        for (int t = 0; t < 2; ++t) {
            int idx = tid * 2 + t;          // 0..511
            int r = idx >> 2;
            int kq = idx & 3;
            float4 v = *reinterpret_cast<const float4*>(Ab + (size_t)r * K + k0 + kq * 4);
            As[kq * 4 + 0][r] = v.x;
            As[kq * 4 + 1][r] = v.y;
            As[kq * 4 + 2][r] = v.z;
            As[kq * 4 + 3][r] = v.w;
        }
        #pragma unroll
        for (int t = 0; t < 2; ++t) {
            int idx = tid * 2 + t;
            int kk = idx >> 5;              // 0..15
            int c4 = idx & 31;
            int col = colBase + c4 * 4;
            float4 v = make_float4(0.f, 0.f, 0.f, 0.f);
            if (col < N)
                v = *reinterpret_cast<const float4*>(Bb + (size_t)(k0 + kk) * N + col);
            *reinterpret_cast<float4*>(&Bs[kk][c4 * 4]) = v;
        }
        __syncthreads();
        #pragma unroll
        for (int k = 0; k < BK; ++k) {
            float4 a0 = *reinterpret_cast<const float4*>(&As[k][ty * TM]);
            float4 a1 = *reinterpret_cast<const float4*>(&As[k][ty * TM + 4]);
            float4 b0 = *reinterpret_cast<const float4*>(&Bs[k][tx * TN]);
            float4 b1 = *reinterpret_cast<const float4*>(&Bs[k][tx * TN + 4]);
            float a[TM] = {a0.x, a0.y, a0.z, a0.w, a1.x, a1.y, a1.z, a1.w};
            float b[TN] = {b0.x, b0.y, b0.z, b0.w, b1.x, b1.y, b1.z, b1.w};
            #pragma unroll
            for (int j = 0; j < TM; j++)
                #pragma unroll
                for (int i = 0; i < TN; i++)
                    acc[j][i] += a[j] * b[i];
        }
        __syncthreads();
    }

    if (MODE == 0) {
        #pragma unroll
        for (int j = 0; j < TM; j++) {
            int row = rowBase + ty * TM + j;
            #pragma unroll
            for (int i = 0; i < TN; i++) {
                int col = colBase + tx * TN + i;
                if (col < N) {
                    float v = acc[j][i] + bias[col];
                    if (relu) v = fmaxf(v, 0.f);
                    out[(size_t)row * N + col] = v;
                }
            }
        }
    } else if (MODE == 1) {
        int ph = z >> 1, pw = z & 1;
        int OW = 2 * Wq;
        #pragma unroll
        for (int j = 0; j < TM; j++) {
            int row = rowBase + ty * TM + j;
            int n = row / (Hq * Wq);
            int rem = row % (Hq * Wq);
            int r = rem / Wq, c = rem % Wq;
            size_t base = ((size_t)(n * 2 * Hq + 2 * r + ph) * OW + (2 * c + pw)) * N;
            #pragma unroll
            for (int i = 0; i < TN; i++) {
                int col = colBase + tx * TN + i;
                if (col < N) {
                    float v = acc[j][i] + bias[col];
                    if (relu) v = fmaxf(v, 0.f);
                    out[base + col] = v;
                }
            }
        }
    } else { // MODE 2: argmax
        #pragma unroll
        for (int j = 0; j < TM; j++) {
            int row = rowBase + ty * TM + j;
            float best = -INFINITY;
            int bi = 0;
            #pragma unroll
            for (int i = 0; i < TN; i++) {
                int col = colBase + tx * TN + i;
                float v = acc[j][i];
                if (v > best) { best = v; bi = col; }
            }
            unsigned long long key =
                ((unsigned long long)ford(best) << 32) | (0xFFFFFFFFu - (unsigned)bi);
            #pragma unroll
            for (int m = 8; m >= 1; m >>= 1) {
                unsigned long long o = __shfl_xor_sync(0xffffffffu, key, m, 16);
                if (o > key) key = o;
            }
            if (tx == 0) atomicMax(&amax[row], key);
        }
    }
}

// ---------------- gather quantized vectors + emit indices -------------------
__global__ void gather_q(const unsigned long long* __restrict__ am,
                         const float* __restrict__ cb,
                         float* __restrict__ q, float* __restrict__ idx_out)
{
    int gid = blockIdx.x * THREADS + threadIdx.x;  // 16384 * 64
    int row = gid >> 6;
    int c4 = gid & 63;
    unsigned code = 0xFFFFFFFFu - (unsigned)(am[row] & 0xFFFFFFFFull);
    float4 v = *reinterpret_cast<const float4*>(cb + (size_t)code * 256 + c4 * 4);
    *reinterpret_cast<float4*>(q + (size_t)row * 256 + c4 * 4) = v;
    if (c4 == 0 && idx_out) idx_out[row] = (float)code;
}

// ---------------- deconv3: direct, Cout=3, NHWC in -> NCHW out --------------
__global__ void deconv3_k(const float* __restrict__ in, const float* __restrict__ w,
                          const float* __restrict__ b, float* __restrict__ out)
{
    __shared__ float ws[3 * 64 * 16];
    for (int i = threadIdx.x; i < 3072; i += THREADS) ws[i] = w[i];
    __syncthreads();
    int gid = blockIdx.x * THREADS + threadIdx.x;  // 16*256*256 = 2^20
    int ow = gid & 255;
    int oh = (gid >> 8) & 255;
    int n  = gid >> 16;
    int ph = oh & 1, pw = ow & 1;
    int r = oh >> 1, c = ow >> 1;
    float a0 = b[0], a1 = b[1], a2 = b[2];
    #pragma unroll
    for (int th = 0; th < 2; th++) {
        int ih = r + th - 1 + ph;
        if ((unsigned)ih >= 128u) continue;
        int kh = 2 * th + ph;
        #pragma unroll
        for (int tw = 0; tw < 2; tw++) {
            int iw = c + tw - 1 + pw;
            if ((unsigned)iw >= 128u) continue;
            int kw = 2 * tw + pw;
            const float* xp = in + ((size_t)(n * 128 + ih) * 128 + iw) * 64;
            int wo = kh * 4 + kw;
            #pragma unroll
            for (int c4 = 0; c4 < 16; c4++) {
                float4 xv = *reinterpret_cast<const float4*>(xp + c4 * 4);
                int ci = c4 * 4;
                a0 += xv.x * ws[(0 * 64 + ci) * 16 + wo] + xv.y * ws[(0 * 64 + ci + 1) * 16 + wo]
                    + xv.z * ws[(0 * 64 + ci + 2) * 16 + wo] + xv.w * ws[(0 * 64 + ci + 3) * 16 + wo];
                a1 += xv.x * ws[(1 * 64 + ci) * 16 + wo] + xv.y * ws[(1 * 64 + ci + 1) * 16 + wo]
                    + xv.z * ws[(1 * 64 + ci + 2) * 16 + wo] + xv.w * ws[(1 * 64 + ci + 3) * 16 + wo];
                a2 += xv.x * ws[(2 * 64 + ci) * 16 + wo] + xv.y * ws[(2 * 64 + ci + 1) * 16 + wo]
                    + xv.z * ws[(2 * 64 + ci + 2) * 16 + wo] + xv.w * ws[(2 * 64 + ci + 3) * 16 + wo];
            }
        }
    }
    size_t p = (size_t)n * 3 * 65536 + (size_t)oh * 256 + ow;
    out[p] = a0;
    out[p + 65536] = a1;
    out[p + 2 * 65536] = a2;
}

// ---------------------------------------------------------------------------
extern "C" void kernel_launch(void* const* d_in, const int* in_sizes, int n_in,
                              void* d_out, int out_size)
{
    const float* x   = (const float*)d_in[0];
    const float* ew1 = (const float*)d_in[1];
    const float* eb1 = (const float*)d_in[2];
    const float* ew2 = (const float*)d_in[3];
    const float* eb2 = (const float*)d_in[4];
    const float* ew3 = (const float*)d_in[5];
    const float* eb3 = (const float*)d_in[6];
    const float* cb  = (const float*)d_in[7];
    const float* dw1 = (const float*)d_in[8];
    const float* db1 = (const float*)d_in[9];
    const float* dw2 = (const float*)d_in[10];
    const float* db2 = (const float*)d_in[11];
    const float* dw3 = (const float*)d_in[12];
    const float* db3 = (const float*)d_in[13];
    float* out = (float*)d_out;

    float *h1, *col, *h2, *feat, *q, *d1, *d2, *wp;
    unsigned long long* am;
    cudaGetSymbolAddress((void**)&h1,   g_h1);
    cudaGetSymbolAddress((void**)&col,  g_col);
    cudaGetSymbolAddress((void**)&h2,   g_h2);
    cudaGetSymbolAddress((void**)&feat, g_feat);
    cudaGetSymbolAddress((void**)&q,    g_q);
    cudaGetSymbolAddress((void**)&d1,   g_d1);
    cudaGetSymbolAddress((void**)&d2,   g_d2);
    cudaGetSymbolAddress((void**)&wp,   g_wp);
    cudaGetSymbolAddress((void**)&am,   g_amax);

    const int RECON = 16 * 3 * 256 * 256;                 // 3145728
    float* idx_out = (out_size >= RECON + 16384) ? (out + RECON) : nullptr;

    // encoder -----------------------------------------------------------------
    conv1_k<<<65536, THREADS>>>(x, ew1, eb1, h1);

    pack_w_conv<<<(16 * 64 * 128 + THREADS - 1) / THREADS, THREADS>>>(ew2, wp, 64, 128);
    im2col_conv<<<(long long)65536 * 1024 / 4 / THREADS, THREADS>>>(h1, col, 128, 128, 64, 64, 64);
    gemm_k<0><<<dim3(1, 512, 1), THREADS>>>(col, wp, 65536, 128, 1024, eb2, 1, h2, 0, 0, nullptr);

    pack_w_conv<<<(16 * 128 * 256 + THREADS - 1) / THREADS, THREADS>>>(ew3, wp, 128, 256);
    im2col_conv<<<(long long)16384 * 2048 / 4 / THREADS, THREADS>>>(h2, col, 64, 64, 128, 32, 32);
    gemm_k<0><<<dim3(2, 128, 1), THREADS>>>(col, wp, 16384, 256, 2048, eb3, 0, feat, 0, 0, nullptr);

    // quantize ----------------------------------------------------------------
    init_amax<<<64, THREADS>>>(am);
    transpose_cb<<<dim3(8, 256), dim3(32, 8)>>>(cb, wp);
    gemm_k<2><<<dim3(64, 128, 1), THREADS>>>(feat, wp, 16384, 8192, 256, nullptr, 0,
                                             nullptr, 0, 0, am);
    gather_q<<<4096, THREADS>>>(am, cb, q, idx_out);

    // decoder -----------------------------------------------------------------
    pack_w_deconv<<<(4 * 1024 * 128 + THREADS - 1) / THREADS, THREADS>>>(dw1, wp, 256, 128);
    im2col_deconv<<<(long long)4 * 16384 * 1024 / 4 / THREADS, THREADS>>>(q, col, 32, 32, 256);
    gemm_k<1><<<dim3(1, 128, 4), THREADS>>>(col, wp, 16384, 128, 1024, db1, 1, d1, 32, 32, nullptr);

    pack_w_deconv<<<(4 * 512 * 64 + THREADS - 1) / THREADS, THREADS>>>(dw2, wp, 128, 64);
    im2col_deconv<<<(long long)4 * 65536 * 512 / 4 / THREADS, THREADS>>>(d1, col, 64, 64, 128);
    gemm_k<1><<<dim3(1, 512, 4), THREADS>>>(col, wp, 65536, 64, 512, db2, 1, d2, 64, 64, nullptr);

    deconv3_k<<<4096, THREADS>>>(d2, dw3, db3, out);
}

// round 3
// speedup vs baseline: 1.3839x; 1.3839x over previous
#include <cuda_runtime.h>
#include <cuda_bf16.h>
#include <math.h>
#include <stdint.h>

#define THREADS 256

// ---------------- scratch (device globals; no allocation allowed) ----------
__device__ float g_h1  [16u*128u*128u*64u];     // conv1 out NHWC
__device__ float g_col [134217728u];            // im2col scratch / scores bf16
__device__ float g_h2  [65536u*128u];           // conv2 out [rows,C] / cb bf16
__device__ float g_feat[16384u*256u];           // conv3 out == flat [B*HW, C]
__device__ float g_q   [16384u*256u];           // quantized NHWC
__device__ float g_d1  [16u*64u*64u*128u];      // deconv1 out NHWC
__device__ float g_d2  [16u*128u*128u*64u];     // deconv2 out NHWC
__device__ float g_wp  [8192u*256u];            // packed weights / feat bf16

// ---------------- helpers ----------------------------------------------------
__device__ __forceinline__ uint32_t smem_u32(const void* p) {
    uint32_t a;
    asm("{ .reg .u64 t; cvta.to.shared.u64 t, %1; cvt.u32.u64 %0, t; }" : "=r"(a) : "l"(p));
    return a;
}
#define CP_ASYNC16(dst, src) \
    asm volatile("cp.async.cg.shared.global [%0], [%1], 16;" :: "r"(dst), "l"(src) : "memory")
#define CP_COMMIT() asm volatile("cp.async.commit_group;" ::: "memory")
#define CP_WAIT0()  asm volatile("cp.async.wait_group 0;" ::: "memory")

__device__ __forceinline__ unsigned ford(float f) {
    unsigned u = __float_as_uint(f);
    return (u & 0x80000000u) ? ~u : (u | 0x80000000u);
}
__device__ __forceinline__ float iford(unsigned e) {
    return (e & 0x80000000u) ? __uint_as_float(e ^ 0x80000000u) : __uint_as_float(~e);
}

// ---------------- conv1: direct, Cin=3, NCHW in -> NHWC out -----------------
__global__ void conv1_k(const float* __restrict__ x, const float* __restrict__ w,
                        const float* __restrict__ b, float* __restrict__ y)
{
    __shared__ float ws[64 * 48];
    for (int i = threadIdx.x; i < 64 * 48; i += THREADS) ws[i] = w[i];
    __syncthreads();
    unsigned gid = blockIdx.x * THREADS + threadIdx.x;
    int co = gid & 63;
    int ow = (gid >> 6) & 127;
    int oh = (gid >> 13) & 127;
    int n  = gid >> 20;
    float acc = b[co];
    #pragma unroll
    for (int kh = 0; kh < 4; kh++) {
        int ih = 2 * oh + kh - 1;
        if ((unsigned)ih >= 256u) continue;
        #pragma unroll
        for (int kw = 0; kw < 4; kw++) {
            int iw = 2 * ow + kw - 1;
            if ((unsigned)iw >= 256u) continue;
            #pragma unroll
            for (int ci = 0; ci < 3; ci++) {
                acc += x[((size_t)(n * 3 + ci) * 256 + ih) * 256 + iw]
                     * ws[co * 48 + ci * 16 + kh * 4 + kw];
            }
        }
    }
    y[gid] = fmaxf(acc, 0.f);
}

// ---------------- im2col (bitwise, all dims pow2) ---------------------------
template<int LC, int LWO>
__global__ void im2col_conv_k(const float* __restrict__ in, float* __restrict__ A)
{
    constexpr unsigned C = 1u << LC, WO = 1u << LWO, WIN = 2u << LWO;
    unsigned gid = blockIdx.x * THREADS + threadIdx.x;
    unsigned kqi = gid & (4 * C - 1);
    unsigned row = gid >> (LC + 2);
    unsigned k = kqi * 4;
    unsigned ci = k & (C - 1);
    unsigned kidx = k >> LC;
    int kh = kidx >> 2, kw = kidx & 3;
    unsigned ow = row & (WO - 1), oh = (row >> LWO) & (WO - 1), n = row >> (2 * LWO);
    int ih = 2 * (int)oh + kh - 1, iw = 2 * (int)ow + kw - 1;
    float4 v = make_float4(0.f, 0.f, 0.f, 0.f);
    if ((unsigned)ih < WIN && (unsigned)iw < WIN)
        v = *reinterpret_cast<const float4*>(in + ((size_t)(n * WIN + ih) * WIN + iw) * C + ci);
    *reinterpret_cast<float4*>(A + (size_t)row * (16 * C) + k) = v;
}

template<int LC, int LWQ>
__global__ void im2col_deconv_k(const float* __restrict__ in, float* __restrict__ A)
{
    constexpr unsigned C = 1u << LC, WQ = 1u << LWQ;
    constexpr unsigned LPC = 4 + 2 * LWQ + LC;   // log2 float4s per class
    unsigned gid = blockIdx.x * THREADS + threadIdx.x;
    unsigned cls = gid >> LPC;
    unsigned g2 = gid & ((1u << LPC) - 1);
    int ph = cls >> 1, pw = cls & 1;
    unsigned kqi = g2 & (C - 1);
    unsigned row = g2 >> LC;
    unsigned k = kqi * 4;
    unsigned ci = k & (C - 1);
    unsigned kidx = kqi >> (LC - 2);
    int th = kidx >> 1, tw = kidx & 1;
    unsigned c = row & (WQ - 1), r = (row >> LWQ) & (WQ - 1), n = row >> (2 * LWQ);
    int ih = (int)r + th - 1 + ph, iw = (int)c + tw - 1 + pw;
    float4 v = make_float4(0.f, 0.f, 0.f, 0.f);
    if ((unsigned)ih < WQ && (unsigned)iw < WQ)
        v = *reinterpret_cast<const float4*>(in + ((size_t)(n * WQ + ih) * WQ + iw) * C + ci);
    *reinterpret_cast<float4*>(A + ((size_t)cls * 16 * WQ * WQ + row) * (4 * C) + k) = v;
}

// ---------------- weight packing --------------------------------------------
__global__ void pack_w_conv(const float* __restrict__ w, float* __restrict__ Bp,
                            int Ci, int Co)
{
    int K = 16 * Ci;
    int gid = blockIdx.x * THREADS + threadIdx.x;
    if (gid >= K * Co) return;
    int k = gid / Co, co = gid % Co;
    int ci = k % Ci;
    int kidx = k / Ci;
    int kh = kidx >> 2, kw = kidx & 3;
    Bp[gid] = w[(((size_t)co * Ci + ci) * 4 + kh) * 4 + kw];
}

__global__ void pack_w_deconv(const float* __restrict__ w, float* __restrict__ Bp,
                              int Ci, int Co)
{
    int K = 4 * Ci;
    int gid = blockIdx.x * THREADS + threadIdx.x;
    if (gid >= 4 * K * Co) return;
    int cls = gid / (K * Co);
    int g2 = gid % (K * Co);
    int k = g2 / Co, co = g2 % Co;
    int ci = k % Ci;
    int kidx = k / Ci;
    int th = kidx >> 1, tw = kidx & 1;
    int kh = 2 * th + (cls >> 1);
    int kw = 2 * tw + (cls & 1);
    Bp[gid] = w[(((size_t)co * Ci + ci) * 4 + kh) * 4 + kw];
}

// ---------------- fp32 -> bf16 conversion ------------------------------------
__global__ void f2bf_k(const float* __restrict__ in, __nv_bfloat16* __restrict__ out)
{
    unsigned i = blockIdx.x * THREADS + threadIdx.x;
    float4 v = reinterpret_cast<const float4*>(in)[i];
    __nv_bfloat162* o = reinterpret_cast<__nv_bfloat162*>(out) + 2u * i;
    o[0] = __nv_bfloat162(__float2bfloat16(v.x), __float2bfloat16(v.y));
    o[1] = __nv_bfloat162(__float2bfloat16(v.z), __float2bfloat16(v.w));
}

// ---------------- SGEMM (fp32) with fused epilogues --------------------------
// MODE 0: out[row*N+col] = relu?(acc + bias[col])
// MODE 1: parity scatter into NHWC [16, 2Hq, 2Wq, N], class = blockIdx.z
template<int MODE, int TN>
__global__ void __launch_bounds__(256, 2)
gemm_k(const float* __restrict__ A, const float* __restrict__ B,
       int M, int N, int K,
       const float* __restrict__ bias, int relu,
       float* __restrict__ out, int Hq, int Wq)
{
    constexpr int BM = 128, BK = 16, BN = 16 * TN, TM = 8;
    __shared__ float As[BK][BM];
    __shared__ float Bs[BK][BN];
    int tid = threadIdx.x;
    int tx = tid & 15, ty = tid >> 4;
    int z = blockIdx.z;
    int rowBase = blockIdx.y * BM;
    int colBase = blockIdx.x * BN;
    const float* Ab = A + (size_t)z * M * K + (size_t)rowBase * K;
    const float* Bb = B + (size_t)z * K * N;
    float acc[TM][TN];
    #pragma unroll
    for (int j = 0; j < TM; j++)
        #pragma unroll
        for (int i = 0; i < TN; i++) acc[j][i] = 0.f;

    for (int k0 = 0; k0 < K; k0 += BK) {
        #pragma unroll
        for (int t = 0; t < 2; ++t) {
            int idx = tid * 2 + t;
            int r = idx >> 2;
            int kq = idx & 3;
            float4 v = *reinterpret_cast<const float4*>(Ab + (size_t)r * K + k0 + kq * 4);
            As[kq * 4 + 0][r] = v.x;
            As[kq * 4 + 1][r] = v.y;
            As[kq * 4 + 2][r] = v.z;
            As[kq * 4 + 3][r] = v.w;
        }
        constexpr int NT = (BK * BN / 4) / 256;
        #pragma unroll
        for (int t = 0; t < NT; ++t) {
            int idx = t * 256 + tid;
            int kk = idx / (BN / 4);
            int c4 = idx % (BN / 4);
            float4 v = *reinterpret_cast<const float4*>(Bb + (size_t)(k0 + kk) * N + colBase + c4 * 4);
            *reinterpret_cast<float4*>(&Bs[kk][c4 * 4]) = v;
        }
        __syncthreads();
        #pragma unroll
        for (int k = 0; k < BK; ++k) {
            float4 a0 = *reinterpret_cast<const float4*>(&As[k][ty * TM]);
            float4 a1 = *reinterpret_cast<const float4*>(&As[k][ty * TM + 4]);
            float a[TM] = {a0.x, a0.y, a0.z, a0.w, a1.x, a1.y, a1.z, a1.w};
            float b[TN];
            #pragma unroll
            for (int q = 0; q < TN / 4; q++) {
                float4 bv = *reinterpret_cast<const float4*>(&Bs[k][tx * TN + q * 4]);
                b[q * 4 + 0] = bv.x; b[q * 4 + 1] = bv.y; b[q * 4 + 2] = bv.z; b[q * 4 + 3] = bv.w;
            }
            #pragma unroll
            for (int j = 0; j < TM; j++)
                #pragma unroll
                for (int i = 0; i < TN; i++)
                    acc[j][i] += a[j] * b[i];
        }
        __syncthreads();
    }

    if (MODE == 0) {
        #pragma unroll
        for (int j = 0; j < TM; j++) {
            int row = rowBase + ty * TM + j;
            #pragma unroll
            for (int i = 0; i < TN; i++) {
                int col = colBase + tx * TN + i;
                float v = acc[j][i] + bias[col];
                if (relu) v = fmaxf(v, 0.f);
                out[(size_t)row * N + col] = v;
            }
        }
    } else {
        int ph = z >> 1, pw = z & 1;
        int OW = 2 * Wq;
        #pragma unroll
        for (int j = 0; j < TM; j++) {
            int row = rowBase + ty * TM + j;
            int n = row / (Hq * Wq);
            int rem = row % (Hq * Wq);
            int r = rem / Wq, c = rem % Wq;
            size_t base = ((size_t)(n * 2 * Hq + 2 * r + ph) * OW + (2 * c + pw)) * N;
            #pragma unroll
            for (int i = 0; i < TN; i++) {
                int col = colBase + tx * TN + i;
                float v = acc[j][i] + bias[col];
                if (relu) v = fmaxf(v, 0.f);
                out[base + col] = v;
            }
        }
    }
}

// ---------------- scores via mma.sync bf16 (HMMA, portable) -----------------
// C[16384,8192] = feat[16384,256] x cb[8192,256]^T, bf16 in, fp32 acc,
// bf16 out. CTA tile 128x128, BK=32, double-buffered cp.async.
__global__ void __launch_bounds__(256, 2)
scores_hmma_k(const __nv_bfloat16* __restrict__ featb,
              const __nv_bfloat16* __restrict__ cbb,
              __nv_bfloat16* __restrict__ scores)
{
    constexpr int LDS = 40;            // bf16 stride (80 B): conflict-free ldmatrix
    __shared__ __align__(16) __nv_bfloat16 As[2][128][LDS];
    __shared__ __align__(16) __nv_bfloat16 Bs[2][128][LDS];
    const int tid = threadIdx.x;
    const int lane = tid & 31, warp = tid >> 5;
    const int wm = warp >> 2, wn = warp & 3;          // warp tile: 64 x 32
    const int mtBase = blockIdx.y * 128, ntBase = blockIdx.x * 128;
    const uint32_t aSm = smem_u32(As), bSm = smem_u32(Bs);

    float acc[4][4][4];
    #pragma unroll
    for (int i = 0; i < 4; i++)
        #pragma unroll
        for (int j = 0; j < 4; j++)
            #pragma unroll
            for (int r = 0; r < 4; r++) acc[i][j][r] = 0.f;

    auto loadTiles = [&](int kt, int buf) {
        int k0 = kt * 32;
        #pragma unroll
        for (int s = 0; s < 2; s++) {
            int idx = s * 256 + tid;
            int row = idx >> 2, c = idx & 3;
            const __nv_bfloat16* srcA = featb + (size_t)(mtBase + row) * 256 + k0 + c * 8;
            const __nv_bfloat16* srcB = cbb   + (size_t)(ntBase + row) * 256 + k0 + c * 8;
            uint32_t da = aSm + (uint32_t)(((buf * 128 + row) * LDS + c * 8) * 2);
            uint32_t db = bSm + (uint32_t)(((buf * 128 + row) * LDS + c * 8) * 2);
            CP_ASYNC16(da, srcA);
            CP_ASYNC16(db, srcB);
        }
    };

    loadTiles(0, 0);
    CP_COMMIT();

    int buf = 0;
    for (int kt = 0; kt < 8; kt++) {
        CP_WAIT0();
        __syncthreads();
        if (kt < 7) { loadTiles(kt + 1, buf ^ 1); CP_COMMIT(); }

        #pragma unroll
        for (int km = 0; km < 2; km++) {
            uint32_t a[4][4], b[4][2];
            #pragma unroll
            for (int mt = 0; mt < 4; mt++) {
                uint32_t addr = aSm + (uint32_t)((((buf * 128 + wm * 64 + mt * 16 + (lane & 15)) * LDS)
                                + km * 16 + ((lane >> 4) * 8)) * 2);
                asm volatile("ldmatrix.sync.aligned.m8n8.x4.shared.b16 {%0,%1,%2,%3}, [%4];"
                             : "=r"(a[mt][0]), "=r"(a[mt][1]), "=r"(a[mt][2]), "=r"(a[mt][3])
                             : "r"(addr));
            }
            #pragma unroll
            for (int nt = 0; nt < 4; nt++) {
                uint32_t addr = bSm + (uint32_t)((((buf * 128 + wn * 32 + nt * 8 + (lane & 7)) * LDS)
                                + km * 16 + (((lane >> 3) & 1) * 8)) * 2);
                asm volatile("ldmatrix.sync.aligned.m8n8.x2.shared.b16 {%0,%1}, [%2];"
                             : "=r"(b[nt][0]), "=r"(b[nt][1]) : "r"(addr));
            }
            #pragma unroll
            for (int mt = 0; mt < 4; mt++)
                #pragma unroll
                for (int nt = 0; nt < 4; nt++)
                    asm volatile(
                        "mma.sync.aligned.m16n8k16.row.col.f32.bf16.bf16.f32 "
                        "{%0,%1,%2,%3}, {%4,%5,%6,%7}, {%8,%9}, {%0,%1,%2,%3};"
                        : "+f"(acc[mt][nt][0]), "+f"(acc[mt][nt][1]),
                          "+f"(acc[mt][nt][2]), "+f"(acc[mt][nt][3])
                        : "r"(a[mt][0]), "r"(a[mt][1]), "r"(a[mt][2]), "r"(a[mt][3]),
                          "r"(b[nt][0]), "r"(b[nt][1]));
        }
        __syncthreads();
        buf ^= 1;
    }

    // epilogue: bf16 stores
    int gr = lane >> 2, gc = (lane & 3) * 2;
    #pragma unroll
    for (int mt = 0; mt < 4; mt++) {
        #pragma unroll
        for (int nt = 0; nt < 4; nt++) {
            int col = ntBase + wn * 32 + nt * 8 + gc;
            size_t r0 = (size_t)(mtBase + wm * 64 + mt * 16 + gr) * 8192 + col;
            size_t r1 = r0 + 8 * 8192;
            *reinterpret_cast<__nv_bfloat162*>(scores + r0) =
                __nv_bfloat162(__float2bfloat16(acc[mt][nt][0]), __float2bfloat16(acc[mt][nt][1]));
            *reinterpret_cast<__nv_bfloat162*>(scores + r1) =
                __nv_bfloat162(__float2bfloat16(acc[mt][nt][2]), __float2bfloat16(acc[mt][nt][3]));
        }
    }
}

// ---------------- argmax with exact fp32 rescue + gather --------------------
__global__ void __launch_bounds__(256)
argmax_rescore_k(const __nv_bfloat16* __restrict__ scores, const float* __restrict__ feat,
                 const float* __restrict__ cb, float* __restrict__ q,
                 float* __restrict__ idx_out)
{
    __shared__ float fsh[256];
    __shared__ unsigned long long keys[256];
    __shared__ float wsum[8];
    __shared__ float marg;
    int row = blockIdx.x, tid = threadIdx.x;

    float fv = feat[(size_t)row * 256 + tid];
    fsh[tid] = fv;
    float ssq = fv * fv;
    #pragma unroll
    for (int m = 16; m; m >>= 1) ssq += __shfl_xor_sync(0xffffffffu, ssq, m);
    if ((tid & 31) == 0) wsum[tid >> 5] = ssq;
    __syncthreads();
    if (tid == 0) {
        float s = 0.f;
        #pragma unroll
        for (int i = 0; i < 8; i++) s += wsum[i];
        marg = 0.12f * sqrtf(s);
    }

    // pass A: approx max over this row
    float sreg[32];
    float bmax = -INFINITY; int bidx = 0;
    const __nv_bfloat16* sr = scores + (size_t)row * 8192;
    #pragma unroll
    for (int t = 0; t < 32; t++) {
        float v = __bfloat162float(sr[t * 256 + tid]);
        sreg[t] = v;
        if (v > bmax) { bmax = v; bidx = t * 256 + tid; }
    }
    keys[tid] = ((unsigned long long)ford(bmax) << 32) | (0xFFFFFFFFu - (unsigned)bidx);
    __syncthreads();
    for (int s = 128; s; s >>= 1) {
        if (tid < s) { unsigned long long o = keys[tid + s]; if (o > keys[tid]) keys[tid] = o; }
        __syncthreads();
    }
    float thr = iford((unsigned)(keys[0] >> 32)) - marg;
    __syncthreads();

    // pass B: exact fp32 rescore of candidates within margin
    unsigned long long ck = 0ull;
    #pragma unroll 1
    for (int t = 0; t < 32; t++) {
        if (sreg[t] >= thr) {
            int j = t * 256 + tid;
            const float* c = cb + (size_t)j * 256;
            float accv = 0.f;
            #pragma unroll 8
            for (int k2 = 0; k2 < 256; k2++) accv += fsh[k2] * c[k2];
            unsigned long long kk = ((unsigned long long)ford(accv) << 32) | (0xFFFFFFFFu - (unsigned)j);
            if (kk > ck) ck = kk;
        }
    }
    keys[tid] = ck;
    __syncthreads();
    for (int s = 128; s; s >>= 1) {
        if (tid < s) { unsigned long long o = keys[tid + s]; if (o > keys[tid]) keys[tid] = o; }
        __syncthreads();
    }
    unsigned code = 0xFFFFFFFFu - (unsigned)(keys[0] & 0xFFFFFFFFull);
    q[(size_t)row * 256 + tid] = cb[(size_t)code * 256 + tid];
    if (tid == 0 && idx_out) idx_out[row] = (float)code;
}

// ---------------- deconv3: direct, Cout=3, NHWC in -> NCHW out --------------
__global__ void deconv3_k(const float* __restrict__ in, const float* __restrict__ w,
                          const float* __restrict__ b, float* __restrict__ out)
{
    __shared__ float ws[3 * 64 * 16];
    for (int i = threadIdx.x; i < 3072; i += THREADS) ws[i] = w[i];
    __syncthreads();
    int gid = blockIdx.x * THREADS + threadIdx.x;
    int ow = gid & 255;
    int oh = (gid >> 8) & 255;
    int n  = gid >> 16;
    int ph = oh & 1, pw = ow & 1;
    int r = oh >> 1, c = ow >> 1;
    float a0 = b[0], a1 = b[1], a2 = b[2];
    #pragma unroll
    for (int th = 0; th < 2; th++) {
        int ih = r + th - 1 + ph;
        if ((unsigned)ih >= 128u) continue;
        int kh = 2 * th + ph;
        #pragma unroll
        for (int tw = 0; tw < 2; tw++) {
            int iw = c + tw - 1 + pw;
            if ((unsigned)iw >= 128u) continue;
            int kw = 2 * tw + pw;
            const float* xp = in + ((size_t)(n * 128 + ih) * 128 + iw) * 64;
            int wo = kh * 4 + kw;
            #pragma unroll
            for (int c4 = 0; c4 < 16; c4++) {
                float4 xv = *reinterpret_cast<const float4*>(xp + c4 * 4);
                int ci = c4 * 4;
                a0 += xv.x * ws[(0 * 64 + ci) * 16 + wo] + xv.y * ws[(0 * 64 + ci + 1) * 16 + wo]
                    + xv.z * ws[(0 * 64 + ci + 2) * 16 + wo] + xv.w * ws[(0 * 64 + ci + 3) * 16 + wo];
                a1 += xv.x * ws[(1 * 64 + ci) * 16 + wo] + xv.y * ws[(1 * 64 + ci + 1) * 16 + wo]
                    + xv.z * ws[(1 * 64 + ci + 2) * 16 + wo] + xv.w * ws[(1 * 64 + ci + 3) * 16 + wo];
                a2 += xv.x * ws[(2 * 64 + ci) * 16 + wo] + xv.y * ws[(2 * 64 + ci + 1) * 16 + wo]
                    + xv.z * ws[(2 * 64 + ci + 2) * 16 + wo] + xv.w * ws[(2 * 64 + ci + 3) * 16 + wo];
            }
        }
    }
    size_t p = (size_t)n * 3 * 65536 + (size_t)oh * 256 + ow;
    out[p] = a0;
    out[p + 65536] = a1;
    out[p + 2 * 65536] = a2;
}

// ---------------------------------------------------------------------------
extern "C" void kernel_launch(void* const* d_in, const int* in_sizes, int n_in,
                              void* d_out, int out_size)
{
    const float* x   = (const float*)d_in[0];
    const float* ew1 = (const float*)d_in[1];
    const float* eb1 = (const float*)d_in[2];
    const float* ew2 = (const float*)d_in[3];
    const float* eb2 = (const float*)d_in[4];
    const float* ew3 = (const float*)d_in[5];
    const float* eb3 = (const float*)d_in[6];
    const float* cb  = (const float*)d_in[7];
    const float* dw1 = (const float*)d_in[8];
    const float* db1 = (const float*)d_in[9];
    const float* dw2 = (const float*)d_in[10];
    const float* db2 = (const float*)d_in[11];
    const float* dw3 = (const float*)d_in[12];
    const float* db3 = (const float*)d_in[13];
    float* out = (float*)d_out;

    float *h1, *col, *h2, *feat, *q, *d1, *d2, *wp;
    cudaGetSymbolAddress((void**)&h1,   g_h1);
    cudaGetSymbolAddress((void**)&col,  g_col);
    cudaGetSymbolAddress((void**)&h2,   g_h2);
    cudaGetSymbolAddress((void**)&feat, g_feat);
    cudaGetSymbolAddress((void**)&q,    g_q);
    cudaGetSymbolAddress((void**)&d1,   g_d1);
    cudaGetSymbolAddress((void**)&d2,   g_d2);
    cudaGetSymbolAddress((void**)&wp,   g_wp);

    const int RECON = 16 * 3 * 256 * 256;
    float* idx_out = (out_size >= RECON + 16384) ? (out + RECON) : nullptr;

    // encoder -----------------------------------------------------------------
    conv1_k<<<65536, THREADS>>>(x, ew1, eb1, h1);

    pack_w_conv<<<512, THREADS>>>(ew2, wp, 64, 128);
    im2col_conv_k<6, 6><<<65536, THREADS>>>(h1, col);
    gemm_k<0, 8><<<dim3(1, 512, 1), THREADS>>>(col, wp, 65536, 128, 1024, eb2, 1, h2, 0, 0);

    pack_w_conv<<<2048, THREADS>>>(ew3, wp, 128, 256);
    im2col_conv_k<7, 5><<<32768, THREADS>>>(h2, col);
    gemm_k<0, 8><<<dim3(2, 128, 1), THREADS>>>(col, wp, 16384, 256, 2048, eb3, 0, feat, 0, 0);

    // quantize: bf16 HMMA scores + exact fp32 rescue --------------------------
    __nv_bfloat16* featb = (__nv_bfloat16*)wp;   // free region now
    __nv_bfloat16* cbb   = (__nv_bfloat16*)h2;   // free region now
    __nv_bfloat16* scb   = (__nv_bfloat16*)col;  // scores bf16 [16384, 8192]
    f2bf_k<<<4096, THREADS>>>(feat, featb);
    f2bf_k<<<2048, THREADS>>>(cb, cbb);

    scores_hmma_k<<<dim3(64, 128), THREADS>>>(featb, cbb, scb);
    argmax_rescore_k<<<16384, THREADS>>>(scb, feat, cb, q, idx_out);

    // decoder -----------------------------------------------------------------
    pack_w_deconv<<<2048, THREADS>>>(dw1, wp, 256, 128);
    im2col_deconv_k<8, 5><<<65536, THREADS>>>(q, col);
    gemm_k<1, 8><<<dim3(1, 128, 4), THREADS>>>(col, wp, 16384, 128, 1024, db1, 1, d1, 32, 32);

    pack_w_deconv<<<512, THREADS>>>(dw2, wp, 128, 64);
    im2col_deconv_k<7, 6><<<131072, THREADS>>>(d1, col);
    gemm_k<1, 4><<<dim3(1, 512, 4), THREADS>>>(col, wp, 65536, 64, 512, db2, 1, d2, 64, 64);

    deconv3_k<<<4096, THREADS>>>(d2, dw3, db3, out);
}

// round 4
// speedup vs baseline: 1.4736x; 1.0648x over previous
#include <cuda_runtime.h>
#include <cuda_bf16.h>
#include <math.h>
#include <stdint.h>

#define THREADS 256

// ---------------- scratch (device globals; no allocation allowed) ----------
__device__ float g_h1  [16u*128u*128u*64u];     // conv1 out NHWC (67MB)
__device__ float g_col [134217728u];            // scores bf16 [16384,8192] (uses 256MB region)
__device__ float g_h2  [65536u*128u];           // conv2 out NHWC / cb bf16
__device__ float g_feat[16384u*256u];           // conv3 out == flat [B*HW, C]
__device__ float g_q   [16384u*256u];           // quantized NHWC
__device__ float g_d1  [16u*64u*64u*128u];      // deconv1 out NHWC
__device__ float g_d2  [16u*128u*128u*64u];     // deconv2 out NHWC
__device__ float g_wp  [8192u*256u];            // packed weights / feat bf16
__device__ __nv_bfloat16 g_fb[16384u*256u];     // feat bf16

// ---------------- helpers ----------------------------------------------------
__device__ __forceinline__ uint32_t smem_u32(const void* p) {
    uint32_t a;
    asm("{ .reg .u64 t; cvta.to.shared.u64 t, %1; cvt.u32.u64 %0, t; }" : "=r"(a) : "l"(p));
    return a;
}
#define CP_ASYNC16(dst, src) \
    asm volatile("cp.async.cg.shared.global [%0], [%1], 16;" :: "r"(dst), "l"(src) : "memory")
#define CP_COMMIT() asm volatile("cp.async.commit_group;" ::: "memory")
#define CP_WAIT0()  asm volatile("cp.async.wait_group 0;" ::: "memory")

__device__ __forceinline__ unsigned ford(float f) {
    unsigned u = __float_as_uint(f);
    return (u & 0x80000000u) ? ~u : (u | 0x80000000u);
}
__device__ __forceinline__ float iford(unsigned e) {
    return (e & 0x80000000u) ? __uint_as_float(e ^ 0x80000000u) : __uint_as_float(~e);
}

// ---------------- conv1: direct, Cin=3, NCHW in -> NHWC out -----------------
__global__ void conv1_k(const float* __restrict__ x, const float* __restrict__ w,
                        const float* __restrict__ b, float* __restrict__ y)
{
    __shared__ float ws[64 * 48];
    for (int i = threadIdx.x; i < 64 * 48; i += THREADS) ws[i] = w[i];
    __syncthreads();
    unsigned gid = blockIdx.x * THREADS + threadIdx.x;
    int co = gid & 63;
    int ow = (gid >> 6) & 127;
    int oh = (gid >> 13) & 127;
    int n  = gid >> 20;
    float acc = b[co];
    #pragma unroll
    for (int kh = 0; kh < 4; kh++) {
        int ih = 2 * oh + kh - 1;
        if ((unsigned)ih >= 256u) continue;
        #pragma unroll
        for (int kw = 0; kw < 4; kw++) {
            int iw = 2 * ow + kw - 1;
            if ((unsigned)iw >= 256u) continue;
            #pragma unroll
            for (int ci = 0; ci < 3; ci++) {
                acc += x[((size_t)(n * 3 + ci) * 256 + ih) * 256 + iw]
                     * ws[co * 48 + ci * 16 + kh * 4 + kw];
            }
        }
    }
    y[gid] = fmaxf(acc, 0.f);
}

// ---------------- weight packing --------------------------------------------
__global__ void pack_w_conv(const float* __restrict__ w, float* __restrict__ Bp,
                            int Ci, int Co)
{
    int K = 16 * Ci;
    int gid = blockIdx.x * THREADS + threadIdx.x;
    if (gid >= K * Co) return;
    int k = gid / Co, co = gid % Co;
    int ci = k % Ci;
    int kidx = k / Ci;
    int kh = kidx >> 2, kw = kidx & 3;
    Bp[gid] = w[(((size_t)co * Ci + ci) * 4 + kh) * 4 + kw];
}

__global__ void pack_w_deconv(const float* __restrict__ w, float* __restrict__ Bp,
                              int Ci, int Co)
{
    int K = 4 * Ci;
    int gid = blockIdx.x * THREADS + threadIdx.x;
    if (gid >= 4 * K * Co) return;
    int cls = gid / (K * Co);
    int g2 = gid % (K * Co);
    int k = g2 / Co, co = g2 % Co;
    int ci = k % Ci;
    int kidx = k / Ci;
    int th = kidx >> 1, tw = kidx & 1;
    int kh = 2 * th + (cls >> 1);
    int kw = 2 * tw + (cls & 1);
    Bp[gid] = w[(((size_t)co * Ci + ci) * 4 + kh) * 4 + kw];
}

// ---------------- fp32 -> bf16 conversion ------------------------------------
__global__ void f2bf_k(const float* __restrict__ in, __nv_bfloat16* __restrict__ out)
{
    unsigned i = blockIdx.x * THREADS + threadIdx.x;
    float4 v = reinterpret_cast<const float4*>(in)[i];
    __nv_bfloat162* o = reinterpret_cast<__nv_bfloat162*>(out) + 2u * i;
    o[0] = __nv_bfloat162(__float2bfloat16(v.x), __float2bfloat16(v.y));
    o[1] = __nv_bfloat162(__float2bfloat16(v.z), __float2bfloat16(v.w));
}

// ---------------- implicit-im2col SGEMM (fp32) -------------------------------
// AMODE 1: A = stride-2 conv patches from NHWC [16, 2^(LW+1), 2^(LW+1), 2^LC]
//          k-order (kh,kw) major, ci minor; BK=16 stays within one (kh,kw).
// AMODE 2: A = deconv parity-class patches from NHWC [16, 2^LW, 2^LW, 2^LC],
//          class = blockIdx.z; k-order (th,tw) major, ci minor.
// MODE 0: out = relu?(acc+bias); MODE 1: parity scatter into NHWC [16,2W,2W,N];
// MODE 2: out fp32 + out2 bf16 (no relu).
template<int AMODE, int LC, int LW, int MODE, int TN>
__global__ void __launch_bounds__(256, 2)
gemm_k(const float* __restrict__ Asrc, const float* __restrict__ B,
       int M, int N, int K,
       const float* __restrict__ bias, int relu,
       float* __restrict__ out, __nv_bfloat16* __restrict__ out2)
{
    constexpr int BM = 128, BK = 16, BN = 16 * TN, TM = 8;
    constexpr unsigned C = 1u << LC;
    constexpr unsigned W = 1u << LW;          // conv: Wo; deconv: Wq
    __shared__ float As[BK][BM];
    __shared__ float Bs[BK][BN];
    int tid = threadIdx.x;
    int tx = tid & 15, ty = tid >> 4;
    int z = blockIdx.z;
    int rowBase = blockIdx.y * BM;
    int colBase = blockIdx.x * BN;
    const float* Bb = B + (size_t)z * K * N;

    // per-thread A row (each thread owns 1 tile row, 2 adjacent float4 k-chunks)
    const int r = tid >> 1;
    const unsigned row = rowBase + r;
    const unsigned cw = row & (W - 1);             // ow / c
    const unsigned rh = (row >> LW) & (W - 1);     // oh / r
    const unsigned n  = row >> (2 * LW);
    const int ph = z >> 1, pw = z & 1;             // deconv parity (AMODE 2)

    float acc[TM][TN];
    #pragma unroll
    for (int j = 0; j < TM; j++)
        #pragma unroll
        for (int i = 0; i < TN; i++) acc[j][i] = 0.f;

    for (int k0 = 0; k0 < K; k0 += BK) {
        #pragma unroll
        for (int t = 0; t < 2; ++t) {
            int kq = (tid & 1) * 2 + t;            // 0..3
            int k = k0 + kq * 4;
            unsigned ci = (unsigned)k & (C - 1);
            int kidx = k >> LC;
            float4 v = make_float4(0.f, 0.f, 0.f, 0.f);
            if (AMODE == 1) {
                int kh = kidx >> 2, kw = kidx & 3;
                int ih = 2 * (int)rh + kh - 1, iw = 2 * (int)cw + kw - 1;
                if ((unsigned)ih < 2 * W && (unsigned)iw < 2 * W)
                    v = *reinterpret_cast<const float4*>(
                        Asrc + ((((size_t)n * 2 * W + ih) * 2 * W + iw) << LC) + ci);
            } else {
                int th = kidx >> 1, tw = kidx & 1;
                int ih = (int)rh + th - 1 + ph, iw = (int)cw + tw - 1 + pw;
                if ((unsigned)ih < W && (unsigned)iw < W)
                    v = *reinterpret_cast<const float4*>(
                        Asrc + ((((size_t)n * W + ih) * W + iw) << LC) + ci);
            }
            As[kq * 4 + 0][r] = v.x;
            As[kq * 4 + 1][r] = v.y;
            As[kq * 4 + 2][r] = v.z;
            As[kq * 4 + 3][r] = v.w;
        }
        constexpr int NT = (BK * BN / 4) / 256;
        #pragma unroll
        for (int t = 0; t < NT; ++t) {
            int idx = t * 256 + tid;
            int kk = idx / (BN / 4);
            int c4 = idx % (BN / 4);
            float4 v = *reinterpret_cast<const float4*>(Bb + (size_t)(k0 + kk) * N + colBase + c4 * 4);
            *reinterpret_cast<float4*>(&Bs[kk][c4 * 4]) = v;
        }
        __syncthreads();
        #pragma unroll
        for (int k = 0; k < BK; ++k) {
            float4 a0 = *reinterpret_cast<const float4*>(&As[k][ty * TM]);
            float4 a1 = *reinterpret_cast<const float4*>(&As[k][ty * TM + 4]);
            float a[TM] = {a0.x, a0.y, a0.z, a0.w, a1.x, a1.y, a1.z, a1.w};
            float b[TN];
            #pragma unroll
            for (int q = 0; q < TN / 4; q++) {
                float4 bv = *reinterpret_cast<const float4*>(&Bs[k][tx * TN + q * 4]);
                b[q * 4 + 0] = bv.x; b[q * 4 + 1] = bv.y; b[q * 4 + 2] = bv.z; b[q * 4 + 3] = bv.w;
            }
            #pragma unroll
            for (int j = 0; j < TM; j++)
                #pragma unroll
                for (int i = 0; i < TN; i++)
                    acc[j][i] += a[j] * b[i];
        }
        __syncthreads();
    }

    if (MODE == 0 || MODE == 2) {
        #pragma unroll
        for (int j = 0; j < TM; j++) {
            int orow = rowBase + ty * TM + j;
            #pragma unroll
            for (int i = 0; i < TN; i++) {
                int col = colBase + tx * TN + i;
                float v = acc[j][i] + bias[col];
                if (MODE == 0 && relu) v = fmaxf(v, 0.f);
                out[(size_t)orow * N + col] = v;
                if (MODE == 2) out2[(size_t)orow * N + col] = __float2bfloat16(v);
            }
        }
    } else {
        int OW = 2 * (int)W;
        #pragma unroll
        for (int j = 0; j < TM; j++) {
            unsigned orow = rowBase + ty * TM + j;
            unsigned cc = orow & (W - 1), rr = (orow >> LW) & (W - 1), nn = orow >> (2 * LW);
            size_t base = ((size_t)(nn * 2 * W + 2 * rr + ph) * OW + (2 * cc + pw)) * N;
            #pragma unroll
            for (int i = 0; i < TN; i++) {
                int col = colBase + tx * TN + i;
                float v = acc[j][i] + bias[col];
                if (relu) v = fmaxf(v, 0.f);
                out[base + col] = v;
            }
        }
    }
}

// ---------------- scores via mma.sync bf16 (HMMA, portable) -----------------
__global__ void __launch_bounds__(256, 2)
scores_hmma_k(const __nv_bfloat16* __restrict__ featb,
              const __nv_bfloat16* __restrict__ cbb,
              __nv_bfloat16* __restrict__ scores)
{
    constexpr int LDS = 40;
    __shared__ __align__(16) __nv_bfloat16 As[2][128][LDS];
    __shared__ __align__(16) __nv_bfloat16 Bs[2][128][LDS];
    const int tid = threadIdx.x;
    const int lane = tid & 31, warp = tid >> 5;
    const int wm = warp >> 2, wn = warp & 3;
    const int mtBase = blockIdx.y * 128, ntBase = blockIdx.x * 128;
    const uint32_t aSm = smem_u32(As), bSm = smem_u32(Bs);

    float acc[4][4][4];
    #pragma unroll
    for (int i = 0; i < 4; i++)
        #pragma unroll
        for (int j = 0; j < 4; j++)
            #pragma unroll
            for (int rr = 0; rr < 4; rr++) acc[i][j][rr] = 0.f;

    auto loadTiles = [&](int kt, int buf) {
        int k0 = kt * 32;
        #pragma unroll
        for (int s = 0; s < 2; s++) {
            int idx = s * 256 + tid;
            int row = idx >> 2, c = idx & 3;
            const __nv_bfloat16* srcA = featb + (size_t)(mtBase + row) * 256 + k0 + c * 8;
            const __nv_bfloat16* srcB = cbb   + (size_t)(ntBase + row) * 256 + k0 + c * 8;
            uint32_t da = aSm + (uint32_t)(((buf * 128 + row) * LDS + c * 8) * 2);
            uint32_t db = bSm + (uint32_t)(((buf * 128 + row) * LDS + c * 8) * 2);
            CP_ASYNC16(da, srcA);
            CP_ASYNC16(db, srcB);
        }
    };

    loadTiles(0, 0);
    CP_COMMIT();

    int buf = 0;
    for (int kt = 0; kt < 8; kt++) {
        CP_WAIT0();
        __syncthreads();
        if (kt < 7) { loadTiles(kt + 1, buf ^ 1); CP_COMMIT(); }

        #pragma unroll
        for (int km = 0; km < 2; km++) {
            uint32_t a[4][4], b[4][2];
            #pragma unroll
            for (int mt = 0; mt < 4; mt++) {
                uint32_t addr = aSm + (uint32_t)((((buf * 128 + wm * 64 + mt * 16 + (lane & 15)) * LDS)
                                + km * 16 + ((lane >> 4) * 8)) * 2);
                asm volatile("ldmatrix.sync.aligned.m8n8.x4.shared.b16 {%0,%1,%2,%3}, [%4];"
                             : "=r"(a[mt][0]), "=r"(a[mt][1]), "=r"(a[mt][2]), "=r"(a[mt][3])
                             : "r"(addr));
            }
            #pragma unroll
            for (int nt = 0; nt < 4; nt++) {
                uint32_t addr = bSm + (uint32_t)((((buf * 128 + wn * 32 + nt * 8 + (lane & 7)) * LDS)
                                + km * 16 + (((lane >> 3) & 1) * 8)) * 2);
                asm volatile("ldmatrix.sync.aligned.m8n8.x2.shared.b16 {%0,%1}, [%2];"
                             : "=r"(b[nt][0]), "=r"(b[nt][1]) : "r"(addr));
            }
            #pragma unroll
            for (int mt = 0; mt < 4; mt++)
                #pragma unroll
                for (int nt = 0; nt < 4; nt++)
                    asm volatile(
                        "mma.sync.aligned.m16n8k16.row.col.f32.bf16.bf16.f32 "
                        "{%0,%1,%2,%3}, {%4,%5,%6,%7}, {%8,%9}, {%0,%1,%2,%3};"
                        : "+f"(acc[mt][nt][0]), "+f"(acc[mt][nt][1]),
                          "+f"(acc[mt][nt][2]), "+f"(acc[mt][nt][3])
                        : "r"(a[mt][0]), "r"(a[mt][1]), "r"(a[mt][2]), "r"(a[mt][3]),
                          "r"(b[nt][0]), "r"(b[nt][1]));
        }
        __syncthreads();
        buf ^= 1;
    }

    int gr = lane >> 2, gc = (lane & 3) * 2;
    #pragma unroll
    for (int mt = 0; mt < 4; mt++) {
        #pragma unroll
        for (int nt = 0; nt < 4; nt++) {
            int col = ntBase + wn * 32 + nt * 8 + gc;
            size_t r0 = (size_t)(mtBase + wm * 64 + mt * 16 + gr) * 8192 + col;
            size_t r1 = r0 + 8 * 8192;
            *reinterpret_cast<__nv_bfloat162*>(scores + r0) =
                __nv_bfloat162(__float2bfloat16(acc[mt][nt][0]), __float2bfloat16(acc[mt][nt][1]));
            *reinterpret_cast<__nv_bfloat162*>(scores + r1) =
                __nv_bfloat162(__float2bfloat16(acc[mt][nt][2]), __float2bfloat16(acc[mt][nt][3]));
        }
    }
}

// ---------------- argmax with exact fp32 rescue + gather --------------------
__global__ void __launch_bounds__(256)
argmax_rescore_k(const __nv_bfloat16* __restrict__ scores, const float* __restrict__ feat,
                 const float* __restrict__ cb, float* __restrict__ q,
                 float* __restrict__ idx_out)
{
    __shared__ float fsh[256];
    __shared__ unsigned long long keys[256];
    __shared__ float wsum[8];
    __shared__ float marg;
    int row = blockIdx.x, tid = threadIdx.x;

    float fv = feat[(size_t)row * 256 + tid];
    fsh[tid] = fv;
    float ssq = fv * fv;
    #pragma unroll
    for (int m = 16; m; m >>= 1) ssq += __shfl_xor_sync(0xffffffffu, ssq, m);
    if ((tid & 31) == 0) wsum[tid >> 5] = ssq;
    __syncthreads();
    if (tid == 0) {
        float s = 0.f;
        #pragma unroll
        for (int i = 0; i < 8; i++) s += wsum[i];
        marg = 0.12f * sqrtf(s);
    }

    float sreg[32];
    float bmax = -INFINITY; int bidx = 0;
    const __nv_bfloat16* sr = scores + (size_t)row * 8192;
    #pragma unroll
    for (int t = 0; t < 32; t++) {
        float v = __bfloat162float(sr[t * 256 + tid]);
        sreg[t] = v;
        if (v > bmax) { bmax = v; bidx = t * 256 + tid; }
    }
    keys[tid] = ((unsigned long long)ford(bmax) << 32) | (0xFFFFFFFFu - (unsigned)bidx);
    __syncthreads();
    for (int s = 128; s; s >>= 1) {
        if (tid < s) { unsigned long long o = keys[tid + s]; if (o > keys[tid]) keys[tid] = o; }
        __syncthreads();
    }
    float thr = iford((unsigned)(keys[0] >> 32)) - marg;
    __syncthreads();

    unsigned long long ck = 0ull;
    #pragma unroll 1
    for (int t = 0; t < 32; t++) {
        if (sreg[t] >= thr) {
            int j = t * 256 + tid;
            const float* c = cb + (size_t)j * 256;
            float accv = 0.f;
            #pragma unroll 8
            for (int k2 = 0; k2 < 256; k2++) accv += fsh[k2] * c[k2];
            unsigned long long kk = ((unsigned long long)ford(accv) << 32) | (0xFFFFFFFFu - (unsigned)j);
            if (kk > ck) ck = kk;
        }
    }
    keys[tid] = ck;
    __syncthreads();
    for (int s = 128; s; s >>= 1) {
        if (tid < s) { unsigned long long o = keys[tid + s]; if (o > keys[tid]) keys[tid] = o; }
        __syncthreads();
    }
    unsigned code = 0xFFFFFFFFu - (unsigned)(keys[0] & 0xFFFFFFFFull);
    q[(size_t)row * 256 + tid] = cb[(size_t)code * 256 + tid];
    if (tid == 0 && idx_out) idx_out[row] = (float)code;
}

// ---------------- deconv3: direct, Cout=3, NHWC in -> NCHW out --------------
__global__ void deconv3_k(const float* __restrict__ in, const float* __restrict__ w,
                          const float* __restrict__ b, float* __restrict__ out)
{
    __shared__ float ws[3 * 64 * 16];
    for (int i = threadIdx.x; i < 3072; i += THREADS) ws[i] = w[i];
    __syncthreads();
    int gid = blockIdx.x * THREADS + threadIdx.x;
    int ow = gid & 255;
    int oh = (gid >> 8) & 255;
    int n  = gid >> 16;
    int ph = oh & 1, pw = ow & 1;
    int r = oh >> 1, c = ow >> 1;
    float a0 = b[0], a1 = b[1], a2 = b[2];
    #pragma unroll
    for (int th = 0; th < 2; th++) {
        int ih = r + th - 1 + ph;
        if ((unsigned)ih >= 128u) continue;
        int kh = 2 * th + ph;
        #pragma unroll
        for (int tw = 0; tw < 2; tw++) {
            int iw = c + tw - 1 + pw;
            if ((unsigned)iw >= 128u) continue;
            int kw = 2 * tw + pw;
            const float* xp = in + ((size_t)(n * 128 + ih) * 128 + iw) * 64;
            int wo = kh * 4 + kw;
            #pragma unroll
            for (int c4 = 0; c4 < 16; c4++) {
                float4 xv = *reinterpret_cast<const float4*>(xp + c4 * 4);
                int ci = c4 * 4;
                a0 += xv.x * ws[(0 * 64 + ci) * 16 + wo] + xv.y * ws[(0 * 64 + ci + 1) * 16 + wo]
                    + xv.z * ws[(0 * 64 + ci + 2) * 16 + wo] + xv.w * ws[(0 * 64 + ci + 3) * 16 + wo];
                a1 += xv.x * ws[(1 * 64 + ci) * 16 + wo] + xv.y * ws[(1 * 64 + ci + 1) * 16 + wo]
                    + xv.z * ws[(1 * 64 + ci + 2) * 16 + wo] + xv.w * ws[(1 * 64 + ci + 3) * 16 + wo];
                a2 += xv.x * ws[(2 * 64 + ci) * 16 + wo] + xv.y * ws[(2 * 64 + ci + 1) * 16 + wo]
                    + xv.z * ws[(2 * 64 + ci + 2) * 16 + wo] + xv.w * ws[(2 * 64 + ci + 3) * 16 + wo];
            }
        }
    }
    size_t p = (size_t)n * 3 * 65536 + (size_t)oh * 256 + ow;
    out[p] = a0;
    out[p + 65536] = a1;
    out[p + 2 * 65536] = a2;
}

// ---------------------------------------------------------------------------
extern "C" void kernel_launch(void* const* d_in, const int* in_sizes, int n_in,
                              void* d_out, int out_size)
{
    const float* x   = (const float*)d_in[0];
    const float* ew1 = (const float*)d_in[1];
    const float* eb1 = (const float*)d_in[2];
    const float* ew2 = (const float*)d_in[3];
    const float* eb2 = (const float*)d_in[4];
    const float* ew3 = (const float*)d_in[5];
    const float* eb3 = (const float*)d_in[6];
    const float* cb  = (const float*)d_in[7];
    const float* dw1 = (const float*)d_in[8];
    const float* db1 = (const float*)d_in[9];
    const float* dw2 = (const float*)d_in[10];
    const float* db2 = (const float*)d_in[11];
    const float* dw3 = (const float*)d_in[12];
    const float* db3 = (const float*)d_in[13];
    float* out = (float*)d_out;

    float *h1, *col, *h2, *feat, *q, *d1, *d2, *wp;
    __nv_bfloat16* fb;
    cudaGetSymbolAddress((void**)&h1,   g_h1);
    cudaGetSymbolAddress((void**)&col,  g_col);
    cudaGetSymbolAddress((void**)&h2,   g_h2);
    cudaGetSymbolAddress((void**)&feat, g_feat);
    cudaGetSymbolAddress((void**)&q,    g_q);
    cudaGetSymbolAddress((void**)&d1,   g_d1);
    cudaGetSymbolAddress((void**)&d2,   g_d2);
    cudaGetSymbolAddress((void**)&wp,   g_wp);
    cudaGetSymbolAddress((void**)&fb,   g_fb);

    const int RECON = 16 * 3 * 256 * 256;
    float* idx_out = (out_size >= RECON + 16384) ? (out + RECON) : nullptr;

    // encoder -----------------------------------------------------------------
    conv1_k<<<65536, THREADS>>>(x, ew1, eb1, h1);

    pack_w_conv<<<512, THREADS>>>(ew2, wp, 64, 128);
    // conv2: implicit im2col from h1 (NHWC 128x128x64)
    gemm_k<1, 6, 6, 0, 8><<<dim3(1, 512, 1), THREADS>>>(h1, wp, 65536, 128, 1024, eb2, 1, h2, nullptr);

    pack_w_conv<<<2048, THREADS>>>(ew3, wp, 128, 256);
    // conv3: implicit im2col from h2 (NHWC 64x64x128); fused bf16 feat output
    gemm_k<1, 7, 5, 2, 8><<<dim3(2, 128, 1), THREADS>>>(h2, wp, 16384, 256, 2048, eb3, 0, feat, fb);

    // quantize: bf16 HMMA scores + exact fp32 rescue --------------------------
    __nv_bfloat16* cbb = (__nv_bfloat16*)h2;     // region free now
    __nv_bfloat16* scb = (__nv_bfloat16*)col;    // scores bf16 [16384, 8192]
    f2bf_k<<<2048, THREADS>>>(cb, cbb);

    scores_hmma_k<<<dim3(64, 128), THREADS>>>(fb, cbb, scb);
    argmax_rescore_k<<<16384, THREADS>>>(scb, feat, cb, q, idx_out);

    // decoder -----------------------------------------------------------------
    pack_w_deconv<<<2048, THREADS>>>(dw1, wp, 256, 128);
    gemm_k<2, 8, 5, 1, 8><<<dim3(1, 128, 4), THREADS>>>(q, wp, 16384, 128, 1024, db1, 1, d1, nullptr);

    pack_w_deconv<<<512, THREADS>>>(dw2, wp, 128, 64);
    gemm_k<2, 7, 6, 1, 4><<<dim3(1, 512, 4), THREADS>>>(d1, wp, 65536, 64, 512, db2, 1, d2, nullptr);

    deconv3_k<<<4096, THREADS>>>(d2, dw3, db3, out);
}